// round 1
// baseline (speedup 1.0000x reference)
#include <cuda_runtime.h>

#define BB 8
#define CC 48
#define HH 128
#define HW 16384
#define WR 65
#define NHEADS 4

// ---------------- scratch (device globals; no allocation in kernel_launch) ---
__device__ float g_ap[BB*CC];
__device__ float g_filt[BB*8*9];
__device__ float g_low [BB*CC*HW];
__device__ float g_high[BB*CC*HW];
__device__ float g_hf  [BB*CC*HW];
__device__ float g_lf  [BB*CC*HW];
__device__ float g_freq[BB*2*CC*HH*WR];
__device__ float g_bufA[BB*CC*HW];
__device__ float g_q   [BB*CC*HW];
__device__ float g_bufC[BB*2*CC*HW];
__device__ float g_kvh [BB*2*CC*HW];
__device__ float g_kvl [BB*2*CC*HW];
__device__ float g_G   [2*BB*NHEADS*168];   // per (path,b,head): 144 gram + 12 |q|^2 + 12 |k|^2
__device__ float g_N   [2*BB*CC*CC];        // per-path per-batch fused 48x48 matrices

__device__ __forceinline__ float gelu_exact(float v){
    return 0.5f*v*(1.0f + erff(v*0.70710678118654752440f));
}

// ---------------- K1: per-(b,c) spatial mean -------------------------------
__global__ void k_mean(const float* __restrict__ x){
    int bc = blockIdx.x;
    const float* p = x + (size_t)bc*HW;
    float s = 0.f;
    for (int i = threadIdx.x; i < HW; i += 256) s += p[i];
    __shared__ float sm[256];
    sm[threadIdx.x] = s; __syncthreads();
    for (int o = 128; o; o >>= 1){ if (threadIdx.x < o) sm[threadIdx.x] += sm[threadIdx.x+o]; __syncthreads(); }
    if (threadIdx.x == 0) g_ap[bc] = sm[0] * (1.0f/HW);
}

// ---------------- K2: dynamic filter (1x1 conv + BN + group softmax) --------
__global__ void k_filt(const float* __restrict__ fdw, const float* __restrict__ gg,
                       const float* __restrict__ bb, const float* __restrict__ mm,
                       const float* __restrict__ vv){
    __shared__ float lf[72];
    int b = blockIdx.x, o = threadIdx.x;
    if (o < 72){
        float a = 0.f;
        #pragma unroll
        for (int c = 0; c < CC; c++) a += g_ap[b*CC+c]*fdw[o*CC+c];
        a = (a - mm[o]) * rsqrtf(vv[o] + 1e-5f) * gg[o] + bb[o];
        lf[o] = a;
    }
    __syncthreads();
    if (o < 8){
        float mx = -1e30f;
        for (int k = 0; k < 9; k++) mx = fmaxf(mx, lf[o*9+k]);
        float e[9], s = 0.f;
        for (int k = 0; k < 9; k++){ e[k] = expf(lf[o*9+k]-mx); s += e[k]; }
        for (int k = 0; k < 9; k++) g_filt[(b*8+o)*9+k] = e[k]/s;
    }
}

// ---------------- K3: low = dyn-filter(x) (reflect pad), high = x - low -----
__global__ void k_lowhigh(const float* __restrict__ x){
    int bc = blockIdx.x; int b = bc/CC, c = bc%CC, g = c/6;
    __shared__ float f[9];
    if (threadIdx.x < 9) f[threadIdx.x] = g_filt[(b*8+g)*9+threadIdx.x];
    __syncthreads();
    const float* xp = x + (size_t)bc*HW;
    float* lo = g_low + (size_t)bc*HW;
    float* hi = g_high + (size_t)bc*HW;
    for (int p = threadIdx.x; p < HW; p += 256){
        int h = p >> 7, w = p & 127;
        float acc = 0.f;
        #pragma unroll
        for (int i = 0; i < 3; i++){
            int hh = h + i - 1; hh = hh < 0 ? -hh : (hh > 127 ? 254-hh : hh);
            #pragma unroll
            for (int j = 0; j < 3; j++){
                int ww = w + j - 1; ww = ww < 0 ? -ww : (ww > 127 ? 254-ww : ww);
                acc += f[i*3+j]*xp[hh*128+ww];
            }
        }
        float xv = xp[p];
        lo[p] = acc; hi[p] = xv - acc;
    }
}

// ---------------- K4: fmgm_high: separable (1x3)(3x1) dw conv, gelu gate ----
__global__ void k_fh(const float* __restrict__ w1, const float* __restrict__ b1,
                     const float* __restrict__ w2, const float* __restrict__ b2){
    int bc = blockIdx.x; int c = bc % CC;
    __shared__ float a1[3], a2[3], bb1, bb2;
    if (threadIdx.x < 3){ a1[threadIdx.x] = w1[c*3+threadIdx.x]; a2[threadIdx.x] = w2[c*3+threadIdx.x]; }
    if (threadIdx.x == 0){ bb1 = b1[c]; bb2 = b2[c]; }
    __syncthreads();
    const float* hi = g_high + (size_t)bc*HW;
    float* out = g_hf + (size_t)bc*HW;
    for (int p = threadIdx.x; p < HW; p += 256){
        int h = p >> 7, w = p & 127;
        float acc = bb2;
        #pragma unroll
        for (int i = 0; i < 3; i++){
            int hh = h + i - 1; if (hh < 0 || hh > 127) continue;
            float tt = bb1;
            #pragma unroll
            for (int j = 0; j < 3; j++){
                int ww = w + j - 1; if (ww < 0 || ww > 127) continue;
                tt += a1[j]*hi[hh*128+ww];
            }
            acc += a2[i]*tt;
        }
        out[p] = gelu_exact(acc) * hi[p];
    }
}

// ---------------- warp-cooperative 128-pt radix-2 FFT (shared mem) ----------
// sgn = -1: forward, +1: inverse (no 1/N scaling applied here)
__device__ __forceinline__ void fft128(float2* s, int lane, float sgn){
    #pragma unroll
    for (int r = 0; r < 4; r++){
        int i = lane + r*32;
        int j = (int)(__brev((unsigned)i) >> 25);
        if (i < j){ float2 t = s[i]; s[i] = s[j]; s[j] = t; }
    }
    __syncwarp();
    #pragma unroll
    for (int st = 1; st <= 7; st++){
        int len = 1 << st, half = len >> 1;
        float invh = 1.0f/(float)half;
        #pragma unroll
        for (int r = 0; r < 2; r++){
            int t = lane + r*32;
            int grp = t >> (st-1);
            int pos = t & (half-1);
            int i = grp*len + pos;
            float sp, cp;
            sincospif((float)pos*invh, &sp, &cp);
            float wx = cp, wy = sgn*sp;
            float2 u = s[i]; float2 q = s[i+half];
            float vx = q.x*wx - q.y*wy;
            float vy = q.x*wy + q.y*wx;
            s[i]       = make_float2(u.x+vx, u.y+vy);
            s[i+half]  = make_float2(u.x-vx, u.y-vy);
        }
        __syncwarp();
    }
}

// ---------------- K5: row rFFT of g_low -> g_freq (65 bins) -----------------
__global__ void k_rowfft(){
    __shared__ float2 sm[8][128];
    int w8 = threadIdx.x >> 5, lane = threadIdx.x & 31;
    int wid = blockIdx.x*8 + w8;            // (b,c,h) row id, 49152 total
    float2* s = sm[w8];
    const float* row = g_low + (size_t)wid*128;
    #pragma unroll
    for (int r = 0; r < 4; r++){ int i = lane + r*32; s[i] = make_float2(row[i], 0.f); }
    __syncwarp();
    fft128(s, lane, -1.f);
    int b = wid/(CC*HH); int c = (wid/HH)%CC; int h = wid%HH;
    float* re = g_freq + (size_t)((((b*2+0)*CC + c)*HH) + h)*WR;
    float* im = g_freq + (size_t)((((b*2+1)*CC + c)*HH) + h)*WR;
    for (int k = lane; k < WR; k += 32){ re[k] = s[k].x; im[k] = s[k].y; }
}

// ---------------- K6: column FFT over h (fwd/inv) ---------------------------
__global__ void k_colfft(float sgn){
    __shared__ float2 sm[8][128];
    int w8 = threadIdx.x >> 5, lane = threadIdx.x & 31;
    int wid = blockIdx.x*8 + w8;            // (b,c,wr) col id, 24960 total
    int b = wid/(CC*WR); int r = wid%(CC*WR); int c = r/WR; int wr = r%WR;
    float* re = g_freq + (size_t)(((b*2+0)*CC + c)*HH)*WR + wr;
    float* im = g_freq + (size_t)(((b*2+1)*CC + c)*HH)*WR + wr;
    float2* s = sm[w8];
    #pragma unroll
    for (int rr = 0; rr < 4; rr++){ int h = lane + rr*32; s[h] = make_float2(re[h*WR], im[h*WR]); }
    __syncwarp();
    fft128(s, lane, sgn);
    #pragma unroll
    for (int rr = 0; rr < 4; rr++){ int h = lane + rr*32; re[h*WR] = s[h].x; im[h*WR] = s[h].y; }
}

// ---------------- K7: frequency-domain gated channel mix (in place) ---------
__global__ void k_mix(const float* __restrict__ flw, const float* __restrict__ flb){
    __shared__ float yf[96*WR];
    int b = blockIdx.x / HH, h = blockIdx.x % HH;
    int t = threadIdx.x;
    for (int idx = t; idx < 96*WR; idx += 256){
        int cc = idx/WR, wr = idx%WR;
        int half = cc/CC, c = cc%CC;
        yf[idx] = g_freq[(size_t)((((b*2+half)*CC + c)*HH) + h)*WR + wr];
    }
    __syncthreads();
    for (int task = t; task < 96*WR; task += 256){
        int o = task/WR, wr = task%WR;
        float acc = flb[o];
        const float* wrow = flw + o*96;
        #pragma unroll
        for (int c2 = 0; c2 < 96; c2++) acc += wrow[c2]*yf[c2*WR + wr];
        float ov = yf[task] * gelu_exact(acc);
        int half = o/CC, c = o%CC;
        g_freq[(size_t)((((b*2+half)*CC + c)*HH) + h)*WR + wr] = ov;
    }
}

// ---------------- K8: inverse row FFT (hermitian rebuild) -> g_lf -----------
__global__ void k_rowifft(){
    __shared__ float2 sm[8][128];
    int w8 = threadIdx.x >> 5, lane = threadIdx.x & 31;
    int wid = blockIdx.x*8 + w8;
    int b = wid/(CC*HH); int c = (wid/HH)%CC; int h = wid%HH;
    const float* re = g_freq + (size_t)((((b*2+0)*CC + c)*HH) + h)*WR;
    const float* im = g_freq + (size_t)((((b*2+1)*CC + c)*HH) + h)*WR;
    float2* s = sm[w8];
    for (int k = lane; k < WR; k += 32) s[k] = make_float2(re[k], im[k]);
    __syncwarp();
    for (int k = WR + lane; k < 128; k += 32){ float2 m = s[128-k]; s[k] = make_float2(m.x, -m.y); }
    __syncwarp();
    fft128(s, lane, 1.f);
    float* out = g_lf + (size_t)wid*128;
    #pragma unroll
    for (int rr = 0; rr < 4; rr++){ int i = lane + rr*32; out[i] = s[i].x * (1.0f/16384.0f); }
}

// ---------------- generic 1x1 conv (48 -> COUT) ------------------------------
template<int COUT>
__global__ void k_conv1x1(const float* __restrict__ in, const float* __restrict__ w,
                          float* __restrict__ out){
    __shared__ float si[CC*128];
    __shared__ float sw[COUT*CC];
    int b = blockIdx.y; int p0 = blockIdx.x*128; int t = threadIdx.x;
    for (int idx = t; idx < COUT*CC; idx += 256) sw[idx] = w[idx];
    for (int idx = t; idx < CC*128; idx += 256){
        int c = idx >> 7, p = idx & 127;
        si[idx] = in[(size_t)(b*CC + c)*HW + p0 + p];
    }
    __syncthreads();
    for (int task = t; task < COUT*128; task += 256){
        int o = task >> 7, p = task & 127;
        float acc = 0.f;
        #pragma unroll
        for (int c = 0; c < CC; c++) acc += sw[o*CC + c]*si[c*128 + p];
        out[(size_t)(b*COUT + o)*HW + p0 + p] = acc;
    }
}

// ---------------- depthwise 3x3, zero pad, no bias --------------------------
__global__ void k_dw3(const float* __restrict__ in, const float* __restrict__ w9,
                      float* __restrict__ out, int Ctot){
    int bc = blockIdx.x; int c = bc % Ctot;
    __shared__ float f[9];
    if (threadIdx.x < 9) f[threadIdx.x] = w9[c*9 + threadIdx.x];
    __syncthreads();
    const float* p = in + (size_t)bc*HW;
    float* o = out + (size_t)bc*HW;
    for (int px = threadIdx.x; px < HW; px += 256){
        int h = px >> 7, w = px & 127;
        float acc = 0.f;
        #pragma unroll
        for (int i = 0; i < 3; i++){
            int hh = h + i - 1; if (hh < 0 || hh > 127) continue;
            #pragma unroll
            for (int j = 0; j < 3; j++){
                int ww = w + j - 1; if (ww < 0 || ww > 127) continue;
                acc += f[i*3+j]*p[hh*128+ww];
            }
        }
        o[px] = acc;
    }
}

// ---------------- zero the gram accumulators ---------------------------------
__global__ void k_zeroG(){
    int i = blockIdx.x*256 + threadIdx.x;
    if (i < 2*BB*NHEADS*168) g_G[i] = 0.f;
}

// ---------------- fused gram + squared norms (per b,head, chunked) ----------
__global__ void __launch_bounds__(256,1)
k_gram(const float* __restrict__ q, const float* __restrict__ kv, float* __restrict__ G){
    int bh = blockIdx.x; int b = bh/NHEADS, hd = bh%NHEADS;
    const float* qb = q  + (size_t)(b*CC    + hd*12)*HW + blockIdx.y*1024;
    const float* kb = kv + (size_t)(b*2*CC + hd*12)*HW + blockIdx.y*1024;
    float acc[168];
    #pragma unroll
    for (int i = 0; i < 168; i++) acc[i] = 0.f;
    for (int p = threadIdx.x; p < 1024; p += 256){
        float qv[12], kvv[12];
        #pragma unroll
        for (int d = 0; d < 12; d++){ qv[d] = qb[d*HW + p]; kvv[d] = kb[d*HW + p]; }
        #pragma unroll
        for (int d = 0; d < 12; d++){
            #pragma unroll
            for (int e = 0; e < 12; e++) acc[d*12+e] += qv[d]*kvv[e];
            acc[144+d] += qv[d]*qv[d];
            acc[156+d] += kvv[d]*kvv[d];
        }
    }
    int lane = threadIdx.x & 31;
    float* Gp = G + bh*168;
    #pragma unroll
    for (int i = 0; i < 168; i++){
        float v = acc[i];
        for (int off = 16; off; off >>= 1) v += __shfl_down_sync(0xffffffffu, v, off);
        if (lane == 0) atomicAdd(&Gp[i], v);
    }
}

// ---------------- per-batch fused N = fp_slice @ pw @ BD(softmax(S)) ---------
__global__ void k_prepN(const float* __restrict__ pw, const float* __restrict__ temp,
                        const float* __restrict__ fpw, int path){
    int b = blockIdx.x, t = threadIdx.x;
    __shared__ float A[4*12*12];
    __shared__ float M[48*48];
    const float* Gb = g_G + ((size_t)path*BB + b)*NHEADS*168;
    if (t < 48){
        int hd = t/12, d = t%12;
        const float* Gh = Gb + hd*168;
        float nq = fmaxf(sqrtf(Gh[144+d]), 1e-12f);
        float tp = temp[hd];
        float row[12]; float mx = -1e30f;
        #pragma unroll
        for (int e = 0; e < 12; e++){
            float nk = fmaxf(sqrtf(Gh[156+e]), 1e-12f);
            row[e] = Gh[d*12+e]/(nq*nk)*tp;
            mx = fmaxf(mx, row[e]);
        }
        float s = 0.f;
        #pragma unroll
        for (int e = 0; e < 12; e++){ row[e] = expf(row[e]-mx); s += row[e]; }
        #pragma unroll
        for (int e = 0; e < 12; e++) A[(hd*12+d)*12 + e] = row[e]/s;
    }
    __syncthreads();
    for (int task = t; task < 2304; task += blockDim.x){
        int o = task/48, cg = task%48; int he = cg/12, e = cg%12;
        float acc = 0.f;
        #pragma unroll
        for (int d = 0; d < 12; d++) acc += pw[o*48 + he*12 + d]*A[(he*12+d)*12 + e];
        M[task] = acc;
    }
    __syncthreads();
    float* Nout = g_N + ((size_t)path*BB + b)*2304;
    for (int task = t; task < 2304; task += blockDim.x){
        int o2 = task/48, cg = task%48;
        float acc = 0.f;
        #pragma unroll
        for (int o = 0; o < 48; o++) acc += fpw[o2*96 + path*48 + o]*M[o*48 + cg];
        Nout[task] = acc;
    }
}

// ---------------- final fused: out = Nh@v_h + Nl@v_l + fp_b + x --------------
__global__ void k_final(const float* __restrict__ x, const float* __restrict__ fpb,
                        float* __restrict__ out){
    __shared__ float sv[2*CC*64];
    __shared__ float sn[2*2304];
    int b = blockIdx.y; int p0 = blockIdx.x*64; int t = threadIdx.x;
    for (int idx = t; idx < 2304; idx += 256){
        sn[idx]        = g_N[(size_t)b*2304 + idx];
        sn[2304 + idx] = g_N[(size_t)(BB + b)*2304 + idx];
    }
    for (int idx = t; idx < CC*64; idx += 256){
        int c = idx >> 6, p = idx & 63;
        sv[idx]          = g_kvh[(size_t)(b*2*CC + CC + c)*HW + p0 + p];
        sv[CC*64 + idx]  = g_kvl[(size_t)(b*2*CC + CC + c)*HW + p0 + p];
    }
    __syncthreads();
    for (int task = t; task < CC*64; task += 256){
        int o = task >> 6, p = task & 63;
        float acc = fpb[o];
        #pragma unroll
        for (int c = 0; c < CC; c++) acc += sn[o*CC + c]*sv[c*64 + p];
        #pragma unroll
        for (int c = 0; c < CC; c++) acc += sn[2304 + o*CC + c]*sv[CC*64 + c*64 + p];
        size_t gi = (size_t)(b*CC + o)*HW + p0 + p;
        out[gi] = acc + x[gi];
    }
}

// ============================================================================
extern "C" void kernel_launch(void* const* d_in, const int* in_sizes, int n_in,
                              void* d_out, int out_size){
    const float* x       = (const float*)d_in[0];
    const float* fd_w    = (const float*)d_in[1];
    const float* bn_g    = (const float*)d_in[2];
    const float* bn_b    = (const float*)d_in[3];
    const float* bn_m    = (const float*)d_in[4];
    const float* bn_v    = (const float*)d_in[5];
    const float* fh_w1   = (const float*)d_in[6];
    const float* fh_b1   = (const float*)d_in[7];
    const float* fh_w2   = (const float*)d_in[8];
    const float* fh_b2   = (const float*)d_in[9];
    const float* fl_w    = (const float*)d_in[10];
    const float* fl_b    = (const float*)d_in[11];
    const float* hfa_qw  = (const float*)d_in[12];
    const float* hfa_kvw = (const float*)d_in[13];
    const float* hfa_qdw = (const float*)d_in[14];
    const float* hfa_kvdw= (const float*)d_in[15];
    const float* hfa_pw  = (const float*)d_in[16];
    const float* hfa_t   = (const float*)d_in[17];
    const float* lfa_qw  = (const float*)d_in[18];
    const float* lfa_kvw = (const float*)d_in[19];
    const float* lfa_qdw = (const float*)d_in[20];
    const float* lfa_kvdw= (const float*)d_in[21];
    const float* lfa_pw  = (const float*)d_in[22];
    const float* lfa_t   = (const float*)d_in[23];
    const float* fp_w    = (const float*)d_in[24];
    const float* fp_b    = (const float*)d_in[25];

    float *p_hf, *p_lf, *p_bufA, *p_q, *p_bufC, *p_kvh, *p_kvl, *p_G;
    cudaGetSymbolAddress((void**)&p_hf,   g_hf);
    cudaGetSymbolAddress((void**)&p_lf,   g_lf);
    cudaGetSymbolAddress((void**)&p_bufA, g_bufA);
    cudaGetSymbolAddress((void**)&p_q,    g_q);
    cudaGetSymbolAddress((void**)&p_bufC, g_bufC);
    cudaGetSymbolAddress((void**)&p_kvh,  g_kvh);
    cudaGetSymbolAddress((void**)&p_kvl,  g_kvl);
    cudaGetSymbolAddress((void**)&p_G,    g_G);

    // fd: dynamic low-pass split
    k_mean   <<<BB*CC, 256>>>(x);
    k_filt   <<<BB, 128>>>(fd_w, bn_g, bn_b, bn_m, bn_v);
    k_lowhigh<<<BB*CC, 256>>>(x);

    // high branch gate
    k_fh<<<BB*CC, 256>>>(fh_w1, fh_b1, fh_w2, fh_b2);

    // low branch: rfft2 -> gated channel mix -> irfft2
    k_rowfft <<<6144, 256>>>();
    k_colfft <<<3120, 256>>>(-1.f);
    k_mix    <<<BB*HH, 256>>>(fl_w, fl_b);
    k_colfft <<<3120, 256>>>(1.f);
    k_rowifft<<<6144, 256>>>();

    k_zeroG<<<42, 256>>>();

    // fga high (freq = hf)
    k_conv1x1<48><<<dim3(128, BB), 256>>>(p_hf, hfa_qw, p_bufA);
    k_dw3<<<BB*CC, 256>>>(p_bufA, hfa_qdw, p_q, CC);
    k_conv1x1<96><<<dim3(128, BB), 256>>>(x, hfa_kvw, p_bufC);
    k_dw3<<<BB*96, 256>>>(p_bufC, hfa_kvdw, p_kvh, 96);
    k_gram<<<dim3(BB*NHEADS, 16), 256>>>(p_q, p_kvh, p_G);
    k_prepN<<<BB, 256>>>(hfa_pw, hfa_t, fp_w, 0);

    // fga low (freq = lf)
    k_conv1x1<48><<<dim3(128, BB), 256>>>(p_lf, lfa_qw, p_bufA);
    k_dw3<<<BB*CC, 256>>>(p_bufA, lfa_qdw, p_q, CC);
    k_conv1x1<96><<<dim3(128, BB), 256>>>(x, lfa_kvw, p_bufC);
    k_dw3<<<BB*96, 256>>>(p_bufC, lfa_kvdw, p_kvl, 96);
    k_gram<<<dim3(BB*NHEADS, 16), 256>>>(p_q, p_kvl, p_G + BB*NHEADS*168);
    k_prepN<<<BB, 256>>>(lfa_pw, lfa_t, fp_w, 1);

    // fused attn@v + pw + concat + fp + bias + residual
    k_final<<<dim3(256, BB), 256>>>(x, fp_b, (float*)d_out);
}